// round 4
// baseline (speedup 1.0000x reference)
#include <cuda_runtime.h>

#define RES 128
#define IMG 480
#define NBATCH 16

// Block tile: fixed b; ix in [ixo*32,+32), iz in [izo*32,+32), iy in [iyo*16,+16).
// Prologue A (per thread): zc, 1/zc, ui, uok for 4 iz values (lane spans ix).
// Prologue B (block): vq[iy_local][iz_local] = valid ? rint(v)*IMG : -2^30  (2KB smem)
// Compute: lanes span ix (vi uniform per (iy,iz), ui contiguous -> coherent gather).
// Value math self-selects: invalid lanes use d=0 and zc >> 1/128 forces tdf=trunc -> 0.
// Store: transpose via padded smem, lanes span iz -> coalesced 128B rows.

__global__ __launch_bounds__(256)
void backproj_kernel(const float* __restrict__ depth,
                     const float* __restrict__ fl_arr,
                     const float* __restrict__ cd_arr,
                     float* __restrict__ out)
{
    __shared__ float tile[2][32 * 33];
    __shared__ int vq[16 * 32];          // [iy_local][iz_local]

    const int bid = blockIdx.x;          // 2048 blocks
    const int izo = bid & 3;
    const int ixo = (bid >> 2) & 3;
    const int iyo = (bid >> 4) & 7;
    const int b   = bid >> 7;

    const int tid  = threadIdx.x;
    const int lane = tid & 31;
    const int w    = tid >> 5;           // 0..7

    const float inv_res = 1.0f / (float)RES;
    const float off   = (IMG - 1) * 0.5f;   // 239.5
    const float wmax  = (float)(IMG - 1);   // 479
    const float trunc = inv_res;

    const float fl = __ldg(fl_arr + b);
    const float cd = __ldg(cd_arr + b);

    const int iy0 = iyo * 16;

    // ---- Prologue B: vq table (512 entries, 2 per thread) ----
    #pragma unroll
    for (int e = tid; e < 16 * 32; e += 256) {
        int jy = e >> 5;
        int zl = e & 31;
        int iz = izo * 32 + zl;
        float cz  = ((float)iz + 0.5f) * inv_res - 0.5f;
        float zce = cd - cz;
        float izce = 1.0f / zce;
        float flyj = fl * (((float)(iy0 + jy) + 0.5f) * inv_res - 0.5f);
        float v = flyj * izce + off;
        bool vv = (v >= 0.0f) & (v <= wmax);
        vq[e] = vv ? __float2int_rn(v) * IMG : (int)0xC0000000;
    }

    // ---- Prologue A: per-thread iz quantities (iz_local = w + 8k) ----
    const int ix = ixo * 32 + lane;
    const float flx = fl * (((float)ix + 0.5f) * inv_res - 0.5f);

    float zc[4];
    int   ui[4], izl[4];
    bool  uok[4];
    #pragma unroll
    for (int k = 0; k < 4; k++) {
        izl[k] = w + 8 * k;
        int iz = izo * 32 + izl[k];
        float cz = ((float)iz + 0.5f) * inv_res - 0.5f;
        zc[k] = cd - cz;
        float izc = 1.0f / zc[k];
        float u = flx * izc + off;
        ui[k]  = __float2int_rn(u);
        uok[k] = (u >= 0.0f) & (u <= wmax) & (zc[k] > 0.0f);
    }

    const float* __restrict__ ds = depth + (size_t)b * (IMG * IMG);

    // store-phase base: thread stores rows r=w*4+q (ix_local), cols=lane (iz_local)
    const size_t obase = ((size_t)b * RES + ixo * 32) * (RES * RES)
                       + (size_t)izo * 32 + lane;

    __syncthreads();   // vq table ready

    #pragma unroll 2
    for (int j = 0; j < 16; j++) {
        const int buf = j & 1;

        #pragma unroll
        for (int k = 0; k < 4; k++) {
            int q = vq[j * 32 + izl[k]];        // LDS broadcast
            bool ok = (q >= 0) & uok[k];
            float d = 0.0f;
            if (ok) d = __ldg(ds + q + ui[k]);
            // invalid -> d=0, |zc| > trunc  => value 0 automatically
            tile[buf][lane * 33 + izl[k]] =
                fmaf(-(float)RES, fminf(fabsf(zc[k] - d), trunc), 1.0f);
        }

        __syncthreads();

        const size_t oy = obase + (size_t)(iy0 + j) * RES;
        #pragma unroll
        for (int qq = 0; qq < 4; qq++) {
            int r = w * 4 + qq;
            out[oy + (size_t)r * (RES * RES)] = tile[buf][r * 33 + lane];
        }
        // double buffer: next iteration's barrier orders reuse
    }
}

extern "C" void kernel_launch(void* const* d_in, const int* in_sizes, int n_in,
                              void* d_out, int out_size)
{
    const float* depth = (const float*)d_in[0];
    const float* fl    = (const float*)d_in[1];
    const float* cd    = (const float*)d_in[2];
    float* out = (float*)d_out;

    const unsigned grid = NBATCH * 8 * 4 * 4;   // 2048 blocks
    backproj_kernel<<<grid, 256>>>(depth, fl, cd, out);
}

// round 5
// speedup vs baseline: 1.7993x; 1.7993x over previous
#include <cuda_runtime.h>

#define RES 128
#define IMG 480
#define NBATCH 16

#define CACHE_W 96
#define CACHE_H 64
#define CACHE_PITCH 97   // odd pitch -> scattered banks

// Block: fixed b; ix in [ixo*32,+32), iz in [izo*32,+32), iy in [iyo*16,+16).
// Thread: ix = ixo*32 + w*4 + (lane>>3); iz quad = izo*32 + (lane&7)*4 .. +3.
// Phase 1: load the block's depth window (<=96x64 px) into smem.
// Phase 2: per (iy, k): v via FFMA, gather via LDS, value math, STG.128 direct
//          (lanes span iz -> coalesced). No barriers in the loop.
// Invalid voxels: d=0 and zc >> 1/128 => min(|zc-d|,trunc)=trunc => value 0.

__global__ __launch_bounds__(256)
void backproj_kernel(const float* __restrict__ depth,
                     const float* __restrict__ fl_arr,
                     const float* __restrict__ cd_arr,
                     float* __restrict__ out)
{
    __shared__ float win[CACHE_H * CACHE_PITCH];

    const int bid = blockIdx.x;          // 2048 blocks
    const int izo = bid & 3;
    const int ixo = (bid >> 2) & 3;
    const int iyo = (bid >> 4) & 7;
    const int b   = bid >> 7;

    const int tid  = threadIdx.x;
    const int lane = tid & 31;
    const int w    = tid >> 5;           // 0..7

    const float inv_res = 1.0f / (float)RES;
    const float off   = (IMG - 1) * 0.5f;   // 239.5
    const float wmax  = (float)(IMG - 1);   // 479
    const float trunc = inv_res;

    const float fl = __ldg(fl_arr + b);
    const float cd = __ldg(cd_arr + b);

    const int ix  = ixo * 32 + w * 4 + (lane >> 3);
    const int izb = izo * 32 + (lane & 7) * 4;
    const int iy0 = iyo * 16;

    // ---- per-thread prologue: 4 consecutive iz ----
    const float flx = fl * (((float)ix + 0.5f) * inv_res - 0.5f);
    float zc[4];
    int   ui[4];
    bool  uok[4];
    #pragma unroll
    for (int k = 0; k < 4; k++) {
        float cz = ((float)(izb + k) + 0.5f) * inv_res - 0.5f;
        zc[k] = cd - cz;
        float izc = 1.0f / zc[k];
        float u = flx * izc + off;
        ui[k]  = __float2int_rn(u);
        uok[k] = (u >= 0.0f) & (u <= wmax) & (zc[k] > 0.0f);
    }

    // izc needed again in the loop: recompute storage
    float izc[4];
    #pragma unroll
    for (int k = 0; k < 4; k++) izc[k] = 1.0f / zc[k];

    // ---- window bounds from projection corners (block-uniform) ----
    const float cx_lo = ((float)(ixo * 32)      + 0.5f) * inv_res - 0.5f;
    const float cx_hi = ((float)(ixo * 32 + 31) + 0.5f) * inv_res - 0.5f;
    const float cy_lo = ((float)(iy0)           + 0.5f) * inv_res - 0.5f;
    const float cy_hi = ((float)(iy0 + 15)      + 0.5f) * inv_res - 0.5f;
    const float zc_a  = cd - (((float)(izo * 32)      + 0.5f) * inv_res - 0.5f);
    const float zc_b  = cd - (((float)(izo * 32 + 31) + 0.5f) * inv_res - 0.5f);
    const float ia = 1.0f / zc_a, ib = 1.0f / zc_b;

    float u00 = fl * cx_lo * ia + off, u01 = fl * cx_lo * ib + off;
    float u10 = fl * cx_hi * ia + off, u11 = fl * cx_hi * ib + off;
    float v00 = fl * cy_lo * ia + off, v01 = fl * cy_lo * ib + off;
    float v10 = fl * cy_hi * ia + off, v11 = fl * cy_hi * ib + off;

    float umin = fminf(fminf(u00, u01), fminf(u10, u11));
    float umax = fmaxf(fmaxf(u00, u01), fmaxf(u10, u11));
    float vmin = fminf(fminf(v00, v01), fminf(v10, v11));
    float vmax = fmaxf(fmaxf(v00, v01), fmaxf(v10, v11));

    int u0 = max(0, (int)floorf(umin) - 1);
    int u1 = min(IMG - 1, (int)ceilf(umax) + 1);
    int v0 = max(0, (int)floorf(vmin) - 1);
    int v1 = min(IMG - 1, (int)ceilf(vmax) + 1);
    const int Wd = u1 - u0 + 1;
    const int Hd = v1 - v0 + 1;

    const float* __restrict__ ds = depth + (size_t)b * (IMG * IMG);
    float* __restrict__ ob = out + (((size_t)(b * RES + ix)) * RES + iy0) * RES + izb;

    const bool fits = (Wd <= CACHE_W) & (Hd <= CACHE_H) & (zc_a > 0.0f) & (zc_b > 0.0f);

    if (fits) {
        // ---- load depth window (clamped redundant cols; rows valid) ----
        if (Wd > 0 && Hd > 0) {
            const int total = Hd * CACHE_W;
            for (int e = tid; e < total; e += 256) {
                int r = e / CACHE_W;
                int c = e - r * CACHE_W;
                int gc = min(u0 + c, IMG - 1);
                win[r * CACHE_PITCH + c] = __ldg(ds + (v0 + r) * IMG + gc);
            }
        }
        __syncthreads();

        int base_k[4];
        #pragma unroll
        for (int k = 0; k < 4; k++)
            base_k[k] = (ui[k] - u0) - v0 * CACHE_PITCH;

        #pragma unroll 4
        for (int j = 0; j < 16; j++) {
            const float fly = fl * (((float)(iy0 + j) + 0.5f) * inv_res - 0.5f);
            float4 r;
            float* rp = &r.x;
            #pragma unroll
            for (int k = 0; k < 4; k++) {
                float v = fly * izc[k] + off;
                bool ok = uok[k] & (v >= 0.0f) & (v <= wmax);
                float d = 0.0f;
                if (ok) d = win[__float2int_rn(v) * CACHE_PITCH + base_k[k]];
                rp[k] = fmaf(-(float)RES, fminf(fabsf(zc[k] - d), trunc), 1.0f);
            }
            *reinterpret_cast<float4*>(ob + j * RES) = r;
        }
    } else {
        // ---- fallback: direct gather (general inputs) ----
        #pragma unroll 4
        for (int j = 0; j < 16; j++) {
            const float fly = fl * (((float)(iy0 + j) + 0.5f) * inv_res - 0.5f);
            float4 r;
            float* rp = &r.x;
            #pragma unroll
            for (int k = 0; k < 4; k++) {
                float v = fly * izc[k] + off;
                bool ok = uok[k] & (v >= 0.0f) & (v <= wmax);
                float d = 0.0f;
                if (ok) d = __ldg(ds + __float2int_rn(v) * IMG + ui[k]);
                rp[k] = fmaf(-(float)RES, fminf(fabsf(zc[k] - d), trunc), 1.0f);
            }
            *reinterpret_cast<float4*>(ob + j * RES) = r;
        }
    }
}

extern "C" void kernel_launch(void* const* d_in, const int* in_sizes, int n_in,
                              void* d_out, int out_size)
{
    const float* depth = (const float*)d_in[0];
    const float* fl    = (const float*)d_in[1];
    const float* cd    = (const float*)d_in[2];
    float* out = (float*)d_out;

    const unsigned grid = NBATCH * 8 * 4 * 4;   // 2048 blocks
    backproj_kernel<<<grid, 256>>>(depth, fl, cd, out);
}

// round 6
// speedup vs baseline: 1.9464x; 1.0818x over previous
#include <cuda_runtime.h>

#define RES 128
#define IMG 480
#define NBATCH 16

#define CACHE_W 96
#define CACHE_H 64
#define CACHE_PITCH 97   // odd pitch -> scattered banks

// Block: fixed b; ix in [ixo*32,+32), iz in [izo*32,+32), iy in [iyo*16,+16).
// Thread: ix = ixo*32 + w*4 + (lane>>3); iz quad = izo*32 + (lane&7)*4 .. +3.
// Corner bounds of u,v over the block tile (bilinear in (c, 1/zc) -> extrema at
// corners) decide a block-uniform ALL-VALID fast path: inner loop has NO
// predicates (7 issue slots/voxel). d<=0 self-selects to 0 because zc >= trunc.
// Checked fallback covers general inputs.

__global__ __launch_bounds__(256)
void backproj_kernel(const float* __restrict__ depth,
                     const float* __restrict__ fl_arr,
                     const float* __restrict__ cd_arr,
                     float* __restrict__ out)
{
    __shared__ float win[CACHE_H * CACHE_PITCH];

    const int bid = blockIdx.x;          // 2048 blocks
    const int izo = bid & 3;
    const int ixo = (bid >> 2) & 3;
    const int iyo = (bid >> 4) & 7;
    const int b   = bid >> 7;

    const int tid  = threadIdx.x;
    const int lane = tid & 31;
    const int w    = tid >> 5;           // 0..7

    const float inv_res = 1.0f / (float)RES;
    const float off   = (IMG - 1) * 0.5f;   // 239.5
    const float wmax  = (float)(IMG - 1);   // 479
    const float trunc = inv_res;

    const float fl = __ldg(fl_arr + b);
    const float cd = __ldg(cd_arr + b);

    const int ix  = ixo * 32 + w * 4 + (lane >> 3);
    const int izb = izo * 32 + (lane & 7) * 4;
    const int iy0 = iyo * 16;

    // ---- per-thread prologue: 4 consecutive iz ----
    const float flx = fl * (((float)ix + 0.5f) * inv_res - 0.5f);
    float zc[4], izc[4];
    int   ui[4];
    #pragma unroll
    for (int k = 0; k < 4; k++) {
        float cz = ((float)(izb + k) + 0.5f) * inv_res - 0.5f;
        zc[k]  = cd - cz;
        izc[k] = 1.0f / zc[k];
        float u = flx * izc[k] + off;
        ui[k]  = __float2int_rn(u);
    }

    // ---- block-uniform corner bounds ----
    const float cx_lo = ((float)(ixo * 32)      + 0.5f) * inv_res - 0.5f;
    const float cx_hi = ((float)(ixo * 32 + 31) + 0.5f) * inv_res - 0.5f;
    const float cy_lo = ((float)(iy0)           + 0.5f) * inv_res - 0.5f;
    const float cy_hi = ((float)(iy0 + 15)      + 0.5f) * inv_res - 0.5f;
    const float zc_a  = cd - (((float)(izo * 32)      + 0.5f) * inv_res - 0.5f);
    const float zc_b  = cd - (((float)(izo * 32 + 31) + 0.5f) * inv_res - 0.5f);
    const float ia = 1.0f / zc_a, ib = 1.0f / zc_b;

    float u00 = fl * cx_lo * ia + off, u01 = fl * cx_lo * ib + off;
    float u10 = fl * cx_hi * ia + off, u11 = fl * cx_hi * ib + off;
    float v00 = fl * cy_lo * ia + off, v01 = fl * cy_lo * ib + off;
    float v10 = fl * cy_hi * ia + off, v11 = fl * cy_hi * ib + off;

    float umin = fminf(fminf(u00, u01), fminf(u10, u11));
    float umax = fmaxf(fmaxf(u00, u01), fmaxf(u10, u11));
    float vmin = fminf(fminf(v00, v01), fminf(v10, v11));
    float vmax = fmaxf(fmaxf(v00, v01), fmaxf(v10, v11));

    int u0 = max(0, (int)floorf(umin) - 1);
    int u1 = min(IMG - 1, (int)ceilf(umax) + 1);
    int v0 = max(0, (int)floorf(vmin) - 1);
    int v1 = min(IMG - 1, (int)ceilf(vmax) + 1);
    const int Wd = u1 - u0 + 1;
    const int Hd = v1 - v0 + 1;

    const float zc_min = fminf(zc_a, zc_b);

    const bool all_valid =
        (zc_min > trunc) &
        (umin >= 0.01f) & (umax <= wmax - 0.01f) &
        (vmin >= 0.01f) & (vmax <= wmax - 0.01f) &
        (Wd <= CACHE_W) & (Hd <= CACHE_H);

    const float* __restrict__ ds = depth + (size_t)b * (IMG * IMG);
    float* __restrict__ ob = out + (((size_t)(b * RES + ix)) * RES + iy0) * RES + izb;

    if (all_valid) {
        // ---- exact-width window load: warp per row stripe, lane per col ----
        for (int r = w; r < Hd; r += 8) {
            const float* src = ds + (v0 + r) * IMG + u0;
            float* dst = win + r * CACHE_PITCH;
            for (int c = lane; c < Wd; c += 32)
                dst[c] = __ldg(src + c);
        }
        __syncthreads();

        int base_k[4];
        #pragma unroll
        for (int k = 0; k < 4; k++)
            base_k[k] = (ui[k] - u0) - v0 * CACHE_PITCH;

        #pragma unroll 4
        for (int j = 0; j < 16; j++) {
            const float fly = fl * (((float)(iy0 + j) + 0.5f) * inv_res - 0.5f);
            float4 r;
            float* rp = &r.x;
            #pragma unroll
            for (int k = 0; k < 4; k++) {
                float v = fly * izc[k] + off;                       // FFMA
                float d = win[__float2int_rn(v) * CACHE_PITCH + base_k[k]]; // F2I+IMAD+LDS
                float t = fminf(fabsf(zc[k] - d), trunc);           // FADD+FMNMX(|.|)
                rp[k] = fmaf(-(float)RES, t, 1.0f);                 // FFMA
            }
            *reinterpret_cast<float4*>(ob + j * RES) = r;
        }
    } else {
        // ---- general fallback: per-voxel checked direct gather ----
        bool uok[4];
        #pragma unroll
        for (int k = 0; k < 4; k++) {
            float u = flx * izc[k] + off;
            uok[k] = (u >= 0.0f) & (u <= wmax) & (zc[k] > 0.0f);
            ui[k] = min(max(ui[k], 0), IMG - 1);
        }
        #pragma unroll 4
        for (int j = 0; j < 16; j++) {
            const float fly = fl * (((float)(iy0 + j) + 0.5f) * inv_res - 0.5f);
            float4 r;
            float* rp = &r.x;
            #pragma unroll
            for (int k = 0; k < 4; k++) {
                float v = fly * izc[k] + off;
                bool ok = uok[k] & (v >= 0.0f) & (v <= wmax);
                float d = 0.0f;
                if (ok) {
                    int vi = min(max(__float2int_rn(v), 0), IMG - 1);
                    d = __ldg(ds + vi * IMG + ui[k]);
                }
                float val = fmaf(-(float)RES, fminf(fabsf(zc[k] - d), trunc), 1.0f);
                rp[k] = (ok & (d > 0.0f)) ? val : 0.0f;
            }
            *reinterpret_cast<float4*>(ob + j * RES) = r;
        }
    }
}

extern "C" void kernel_launch(void* const* d_in, const int* in_sizes, int n_in,
                              void* d_out, int out_size)
{
    const float* depth = (const float*)d_in[0];
    const float* fl    = (const float*)d_in[1];
    const float* cd    = (const float*)d_in[2];
    float* out = (float*)d_out;

    const unsigned grid = NBATCH * 8 * 4 * 4;   // 2048 blocks
    backproj_kernel<<<grid, 256>>>(depth, fl, cd, out);
}

// round 7
// speedup vs baseline: 2.0336x; 1.0448x over previous
#include <cuda_runtime.h>

#define RES 128
#define IMG 480
#define NBATCH 16

#define CACHE_W 96
#define CACHE_H 64
#define CACHE_PITCH 97   // 97 % 32 == 1 -> bank = (vi + col) & 31, well scattered

// Block: fixed b; ix in [ixo*32,+32), iz in [izo*32,+32), iy in [iyo*16,+16).
// Thread: ix = ixo*32 + w*4 + (lane>>3); iz quad = izo*32 + (lane&7)*4 .. +3.
// Fast path (block-uniform corner-bound check): depth window in smem, NO
// per-voxel predicates; d<=0 self-selects via zc >= trunc. ~8 issue slots/voxel.
// Register-trimmed (launch_bounds 256,8 -> <=32 regs) for full occupancy.

__global__ __launch_bounds__(256, 8)
void backproj_kernel(const float* __restrict__ depth,
                     const float* __restrict__ fl_arr,
                     const float* __restrict__ cd_arr,
                     float* __restrict__ out)
{
    __shared__ float win[CACHE_H * CACHE_PITCH];

    const int bid = blockIdx.x;          // 2048 blocks
    const int izo = bid & 3;
    const int ixo = (bid >> 2) & 3;
    const int iyo = (bid >> 4) & 7;
    const int b   = bid >> 7;

    const int tid  = threadIdx.x;
    const int lane = tid & 31;
    const int w    = tid >> 5;           // 0..7

    const float inv_res = 1.0f / (float)RES;
    const float off   = (IMG - 1) * 0.5f;   // 239.5
    const float wmax  = (float)(IMG - 1);   // 479
    const float trunc = inv_res;            // h = 1/128

    const float fl = __ldg(fl_arr + b);
    const float cd = __ldg(cd_arr + b);

    const int ix  = ixo * 32 + w * 4 + (lane >> 3);
    const int izb = izo * 32 + (lane & 7) * 4;
    const int iy0 = iyo * 16;

    // ---- per-thread prologue: 4 consecutive iz ----
    const float flx = fl * (((float)ix + 0.5f) * inv_res - 0.5f);
    const float zc0 = cd - (((float)izb + 0.5f) * inv_res - 0.5f);  // zc[k] = zc0 - k*h
    float izc[4];
    int   ui[4];
    #pragma unroll
    for (int k = 0; k < 4; k++) {
        izc[k] = 1.0f / (zc0 - (float)k * inv_res);
        ui[k]  = __float2int_rn(flx * izc[k] + off);
    }

    // ---- block-uniform corner bounds ----
    const float cx_lo = ((float)(ixo * 32)      + 0.5f) * inv_res - 0.5f;
    const float cx_hi = ((float)(ixo * 32 + 31) + 0.5f) * inv_res - 0.5f;
    const float cy_lo = ((float)(iy0)           + 0.5f) * inv_res - 0.5f;
    const float cy_hi = ((float)(iy0 + 15)      + 0.5f) * inv_res - 0.5f;
    const float zc_a  = cd - (((float)(izo * 32)      + 0.5f) * inv_res - 0.5f);
    const float zc_b  = cd - (((float)(izo * 32 + 31) + 0.5f) * inv_res - 0.5f);
    const float ia = 1.0f / zc_a, ib = 1.0f / zc_b;

    float u00 = fl * cx_lo * ia + off, u01 = fl * cx_lo * ib + off;
    float u10 = fl * cx_hi * ia + off, u11 = fl * cx_hi * ib + off;
    float v00 = fl * cy_lo * ia + off, v01 = fl * cy_lo * ib + off;
    float v10 = fl * cy_hi * ia + off, v11 = fl * cy_hi * ib + off;

    float umin = fminf(fminf(u00, u01), fminf(u10, u11));
    float umax = fmaxf(fmaxf(u00, u01), fmaxf(u10, u11));
    float vmin = fminf(fminf(v00, v01), fminf(v10, v11));
    float vmax = fmaxf(fmaxf(v00, v01), fmaxf(v10, v11));

    int u0 = max(0, (int)floorf(umin) - 1);
    int u1 = min(IMG - 1, (int)ceilf(umax) + 1);
    int v0 = max(0, (int)floorf(vmin) - 1);
    int v1 = min(IMG - 1, (int)ceilf(vmax) + 1);
    const int Wd = u1 - u0 + 1;
    const int Hd = v1 - v0 + 1;

    const bool all_valid =
        (fminf(zc_a, zc_b) > trunc) &
        (umin >= 0.01f) & (umax <= wmax - 0.01f) &
        (vmin >= 0.01f) & (vmax <= wmax - 0.01f) &
        (Wd <= CACHE_W) & (Hd <= CACHE_H);

    const float* __restrict__ ds = depth + (size_t)b * (IMG * IMG);
    float* __restrict__ ob = out + (((size_t)(b * RES + ix)) * RES + iy0) * RES + izb;

    if (all_valid) {
        // ---- exact-width window load: warp per row stripe, lane per col ----
        for (int r = w; r < Hd; r += 8) {
            const float* src = ds + (v0 + r) * IMG + u0;
            float* dst = win + r * CACHE_PITCH;
            for (int c = lane; c < Wd; c += 32)
                dst[c] = __ldg(src + c);
        }
        __syncthreads();

        // precomputed smem pointers: gather addr = wp[k] + vi*CACHE_PITCH
        const float* wp[4];
        #pragma unroll
        for (int k = 0; k < 4; k++)
            wp[k] = win + ((ui[k] - u0) - v0 * CACHE_PITCH);

        float fly = fl * (((float)iy0 + 0.5f) * inv_res - 0.5f);
        const float dfly = fl * inv_res;

        #pragma unroll 4
        for (int j = 0; j < 16; j++, fly += dfly) {
            float4 r;
            float* rp = &r.x;
            #pragma unroll
            for (int k = 0; k < 4; k++) {
                float v = fly * izc[k] + off;                      // FFMA
                float d = wp[k][__float2int_rn(v) * CACHE_PITCH];  // F2I+IMAD+LDS
                float dk = d + (float)k * inv_res;                 // FADD (imm)
                float t = fminf(fabsf(zc0 - dk), trunc);           // FADD+FMNMX|.|
                rp[k] = fmaf(-(float)RES, t, 1.0f);                // FFMA
            }
            *reinterpret_cast<float4*>(ob + j * RES) = r;
        }
    } else {
        // ---- general fallback: per-voxel checked direct gather ----
        bool uok[4];
        #pragma unroll
        for (int k = 0; k < 4; k++) {
            float zck = zc0 - (float)k * inv_res;
            float u = flx * izc[k] + off;
            uok[k] = (u >= 0.0f) & (u <= wmax) & (zck > 0.0f);
            ui[k] = min(max(ui[k], 0), IMG - 1);
        }
        #pragma unroll 2
        for (int j = 0; j < 16; j++) {
            const float fly = fl * (((float)(iy0 + j) + 0.5f) * inv_res - 0.5f);
            float4 r;
            float* rp = &r.x;
            #pragma unroll
            for (int k = 0; k < 4; k++) {
                float zck = zc0 - (float)k * inv_res;
                float v = fly * izc[k] + off;
                bool ok = uok[k] & (v >= 0.0f) & (v <= wmax);
                float d = 0.0f;
                if (ok) {
                    int vi = min(max(__float2int_rn(v), 0), IMG - 1);
                    d = __ldg(ds + vi * IMG + ui[k]);
                }
                float val = fmaf(-(float)RES, fminf(fabsf(zck - d), trunc), 1.0f);
                rp[k] = (ok & (d > 0.0f)) ? val : 0.0f;
            }
            *reinterpret_cast<float4*>(ob + j * RES) = r;
        }
    }
}

extern "C" void kernel_launch(void* const* d_in, const int* in_sizes, int n_in,
                              void* d_out, int out_size)
{
    const float* depth = (const float*)d_in[0];
    const float* fl    = (const float*)d_in[1];
    const float* cd    = (const float*)d_in[2];
    float* out = (float*)d_out;

    const unsigned grid = NBATCH * 8 * 4 * 4;   // 2048 blocks
    backproj_kernel<<<grid, 256>>>(depth, fl, cd, out);
}

// round 8
// speedup vs baseline: 2.2285x; 1.0959x over previous
#include <cuda_runtime.h>

#define RES 128
#define IMG 480
#define NBATCH 16

#define CACHE_W 96       // max unaligned window width (validity check)
#define CACHE_H 48
#define CACHE_PITCH 100  // multiple of 4 (16B-aligned float4 rows); bank=(4*vi+col)&31

// Block: fixed b; ix in [ixo*32,+32), iz in [izo*32,+32), iy in [iyo*8,+8).
// Thread: ix = ixo*32 + w*4 + (lane>>3); iz quad = izo*32 + (lane&7)*4 .. +3.
// Fast path (block-uniform corner-bound check): depth window in smem (float4
// fill), NO per-voxel predicates; d<=0 self-selects via zc >= trunc.
// 4096 blocks -> ~28 blocks/SM sequentially: small drain tail.

__global__ __launch_bounds__(256, 8)
void backproj_kernel(const float* __restrict__ depth,
                     const float* __restrict__ fl_arr,
                     const float* __restrict__ cd_arr,
                     float* __restrict__ out)
{
    __shared__ float win[CACHE_H * CACHE_PITCH];

    const int bid = blockIdx.x;          // 4096 blocks
    const int izo = bid & 3;
    const int ixo = (bid >> 2) & 3;
    const int iyo = (bid >> 4) & 15;
    const int b   = bid >> 8;

    const int tid  = threadIdx.x;
    const int lane = tid & 31;
    const int w    = tid >> 5;           // 0..7

    const float inv_res = 1.0f / (float)RES;
    const float off   = (IMG - 1) * 0.5f;   // 239.5
    const float wmax  = (float)(IMG - 1);   // 479
    const float trunc = inv_res;            // h = 1/128

    const float fl = __ldg(fl_arr + b);
    const float cd = __ldg(cd_arr + b);

    const int ix  = ixo * 32 + w * 4 + (lane >> 3);
    const int izb = izo * 32 + (lane & 7) * 4;
    const int iy0 = iyo * 8;

    // ---- per-thread prologue: 4 consecutive iz ----
    const float flx = fl * (((float)ix + 0.5f) * inv_res - 0.5f);
    const float zc0 = cd - (((float)izb + 0.5f) * inv_res - 0.5f);  // zc[k] = zc0 - k*h
    float izc[4];
    int   ui[4];
    #pragma unroll
    for (int k = 0; k < 4; k++) {
        izc[k] = 1.0f / (zc0 - (float)k * inv_res);
        ui[k]  = __float2int_rn(flx * izc[k] + off);
    }

    // ---- block-uniform corner bounds ----
    const float cx_lo = ((float)(ixo * 32)      + 0.5f) * inv_res - 0.5f;
    const float cx_hi = ((float)(ixo * 32 + 31) + 0.5f) * inv_res - 0.5f;
    const float cy_lo = ((float)(iy0)           + 0.5f) * inv_res - 0.5f;
    const float cy_hi = ((float)(iy0 + 7)       + 0.5f) * inv_res - 0.5f;
    const float zc_a  = cd - (((float)(izo * 32)      + 0.5f) * inv_res - 0.5f);
    const float zc_b  = cd - (((float)(izo * 32 + 31) + 0.5f) * inv_res - 0.5f);
    const float ia = 1.0f / zc_a, ib = 1.0f / zc_b;

    float u00 = fl * cx_lo * ia + off, u01 = fl * cx_lo * ib + off;
    float u10 = fl * cx_hi * ia + off, u11 = fl * cx_hi * ib + off;
    float v00 = fl * cy_lo * ia + off, v01 = fl * cy_lo * ib + off;
    float v10 = fl * cy_hi * ia + off, v11 = fl * cy_hi * ib + off;

    float umin = fminf(fminf(u00, u01), fminf(u10, u11));
    float umax = fmaxf(fmaxf(u00, u01), fmaxf(u10, u11));
    float vmin = fminf(fminf(v00, v01), fminf(v10, v11));
    float vmax = fmaxf(fmaxf(v00, v01), fmaxf(v10, v11));

    int u0 = max(0, (int)floorf(umin) - 1);
    int u1 = min(IMG - 1, (int)ceilf(umax) + 1);
    int v0 = max(0, (int)floorf(vmin) - 1);
    int v1 = min(IMG - 1, (int)ceilf(vmax) + 1);
    const int Wd = u1 - u0 + 1;
    const int Hd = v1 - v0 + 1;

    const bool all_valid =
        (fminf(zc_a, zc_b) > trunc) &
        (umin >= 0.01f) & (umax <= wmax - 0.01f) &
        (vmin >= 0.01f) & (vmax <= wmax - 0.01f) &
        (Wd <= CACHE_W) & (Hd <= CACHE_H);

    const float* __restrict__ ds = depth + (size_t)b * (IMG * IMG);
    float* __restrict__ ob = out + (((size_t)(b * RES + ix)) * RES + iy0) * RES + izb;

    if (all_valid) {
        // ---- float4 window fill: u0 aligned down to 4; warp per row stripe ----
        const int u0a = u0 & ~3;                     // 16B-aligned start
        const int W4  = (u1 - u0a + 4) >> 2;         // float4 count (<=25)
        for (int r = w; r < Hd; r += 8) {
            const float4* src = reinterpret_cast<const float4*>(ds + (v0 + r) * IMG + u0a);
            float4* dst = reinterpret_cast<float4*>(win + r * CACHE_PITCH);
            if (lane < W4) dst[lane] = __ldg(src + lane);
        }
        __syncthreads();

        // precomputed smem pointers: gather addr = wp[k] + vi*CACHE_PITCH
        const float* wp[4];
        #pragma unroll
        for (int k = 0; k < 4; k++)
            wp[k] = win + ((ui[k] - u0a) - v0 * CACHE_PITCH);

        float fly = fl * (((float)iy0 + 0.5f) * inv_res - 0.5f);
        const float dfly = fl * inv_res;

        #pragma unroll 4
        for (int j = 0; j < 8; j++, fly += dfly) {
            float4 r;
            float* rp = &r.x;
            #pragma unroll
            for (int k = 0; k < 4; k++) {
                float v = fly * izc[k] + off;                      // FFMA
                float d = wp[k][__float2int_rn(v) * CACHE_PITCH];  // F2I+IMAD+LDS
                float dk = d + (float)k * inv_res;                 // FADD (imm)
                float t = fminf(fabsf(zc0 - dk), trunc);           // FADD+FMNMX|.|
                rp[k] = fmaf(-(float)RES, t, 1.0f);                // FFMA
            }
            *reinterpret_cast<float4*>(ob + j * RES) = r;
        }
    } else {
        // ---- general fallback: per-voxel checked direct gather ----
        bool uok[4];
        #pragma unroll
        for (int k = 0; k < 4; k++) {
            float zck = zc0 - (float)k * inv_res;
            float u = flx * izc[k] + off;
            uok[k] = (u >= 0.0f) & (u <= wmax) & (zck > 0.0f);
            ui[k] = min(max(ui[k], 0), IMG - 1);
        }
        #pragma unroll 2
        for (int j = 0; j < 8; j++) {
            const float fly = fl * (((float)(iy0 + j) + 0.5f) * inv_res - 0.5f);
            float4 r;
            float* rp = &r.x;
            #pragma unroll
            for (int k = 0; k < 4; k++) {
                float zck = zc0 - (float)k * inv_res;
                float v = fly * izc[k] + off;
                bool ok = uok[k] & (v >= 0.0f) & (v <= wmax);
                float d = 0.0f;
                if (ok) {
                    int vi = min(max(__float2int_rn(v), 0), IMG - 1);
                    d = __ldg(ds + vi * IMG + ui[k]);
                }
                float val = fmaf(-(float)RES, fminf(fabsf(zck - d), trunc), 1.0f);
                rp[k] = (ok & (d > 0.0f)) ? val : 0.0f;
            }
            *reinterpret_cast<float4*>(ob + j * RES) = r;
        }
    }
}

extern "C" void kernel_launch(void* const* d_in, const int* in_sizes, int n_in,
                              void* d_out, int out_size)
{
    const float* depth = (const float*)d_in[0];
    const float* fl    = (const float*)d_in[1];
    const float* cd    = (const float*)d_in[2];
    float* out = (float*)d_out;

    const unsigned grid = NBATCH * 16 * 4 * 4;   // 4096 blocks
    backproj_kernel<<<grid, 256>>>(depth, fl, cd, out);
}